// round 5
// baseline (speedup 1.0000x reference)
#include <cuda_runtime.h>
#include <math_constants.h>

// RandomFeatures, round 5: persistent warps + dynamic quarter-units.
// lane = batch; xs transposed [T][32] in shared (warp-uniform t => bank = lane,
// conflict-free). Dilations 1..4 specialized at compile time (immediate-offset
// LDS, zero address ALU); dynamic-stride fallback for d > 4.
// Counter reset folded into finalize kernel (graph-replay safe).

#define MAX_KLEN 11
#define WARPS_PER_CTA 10
#define NQ 4
#define BGMAX 4
#define KMAX 8192

__device__ int   g_ctr[BGMAX];          // zero-initialized; rf_fin re-zeroes
__device__ float g_scr[(size_t)BGMAX * KMAX * NQ * 64];

// D > 0: compile-time dilation (immediate offsets). D == 0: dynamic stride.
template<int KLEN, int NB, int D>
__device__ __forceinline__ void conv_block(
    const float* __restrict__ xsl,   // xs + lane
    int base, int d, int dpf, int T,
    const float* __restrict__ w, float bs,
    float& mx, float& cnt)
{
    const int dd = (D > 0) ? D : d;
    float Y[NB + KLEN - 1];
    const int last = base + (NB + KLEN - 2) * dd;
    if (base >= 0 && last < T) {                 // warp-uniform fast path
        const float* p = xsl + base * 32;
        if (D > 0) {
#pragma unroll
            for (int t = 0; t < NB + KLEN - 1; t++) Y[t] = p[t * D * 32];
        } else {
#pragma unroll
            for (int t = 0; t < NB + KLEN - 1; t++) Y[t] = p[t * dpf];
        }
    } else {
#pragma unroll
        for (int t = 0; t < NB + KLEN - 1; t++) {
            const int ix = base + t * dd;
            const int ixc = min(max(ix, 0), T - 1);
            float v = xsl[ixc * 32];
            Y[t] = (ix >= 0 && ix < T) ? v : 0.0f;
        }
    }
#pragma unroll
    for (int i = 0; i < NB; i++) {
        float a = bs;
#pragma unroll
        for (int j = 0; j < KLEN; j++) a = fmaf(w[j], Y[i + j], a);
        mx = fmaxf(mx, a);
        cnt += (a > 0.0f) ? 1.0f : 0.0f;
    }
}

template<int KLEN, int D>
__device__ __forceinline__ void conv_range(
    const float* __restrict__ xsl, int r, int pd, int mlo, int mhi,
    int d, int dpf, int T, const float* __restrict__ w, float bs,
    float& mx, float& cnt)
{
    const int dd = (D > 0) ? D : d;
    int m0 = mlo;
    int base = r - pd + m0 * dd;
    for (; m0 + 8 <= mhi; m0 += 8) {
        conv_block<KLEN, 8, D>(xsl, base, d, dpf, T, w, bs, mx, cnt);
        base += 8 * dd;
    }
    if (m0 + 4 <= mhi) { conv_block<KLEN, 4, D>(xsl, base, d, dpf, T, w, bs, mx, cnt); m0 += 4; base += 4 * dd; }
    if (m0 + 2 <= mhi) { conv_block<KLEN, 2, D>(xsl, base, d, dpf, T, w, bs, mx, cnt); m0 += 2; base += 2 * dd; }
    if (m0 < mhi)      { conv_block<KLEN, 1, D>(xsl, base, d, dpf, T, w, bs, mx, cnt); }
}

template<int KLEN, int D>
__device__ __forceinline__ void process_unit(
    const float* __restrict__ xsl, int d, int pd, int ol, int q, int T,
    const float* __restrict__ w, float bs, float& mx, float& cnt)
{
    const int dd  = (D > 0) ? D : d;
    const int dpf = dd * 32;
    const int q0 = (ol - 1) / dd;                // cheap when D constexpr
    const int rr = (ol - 1) - q0 * dd;
    if (dd >= NQ) {
        for (int r = q; r < dd; r += NQ) {
            const int M = (r <= rr) ? q0 + 1 : q0;   // = ceil((ol-r)/dd)
            conv_range<KLEN, D>(xsl, r, pd, 0, M, d, dpf, T, w, bs, mx, cnt);
        }
    } else {
#pragma unroll
        for (int r = 0; r < dd; r++) {
            const int M = (r <= rr) ? q0 + 1 : q0;
            conv_range<KLEN, D>(xsl, r, pd, (q * M) >> 2, ((q + 1) * M) >> 2,
                                d, dpf, T, w, bs, mx, cnt);
        }
    }
}

template<int KLEN>
__device__ __forceinline__ void dispatch_d(
    const float* __restrict__ xsl, int d, int pd, int ol, int q, int T,
    const float* __restrict__ w, float bs, float& mx, float& cnt)
{
    switch (d) {
    case 1: process_unit<KLEN, 1>(xsl, d, pd, ol, q, T, w, bs, mx, cnt); break;
    case 2: process_unit<KLEN, 2>(xsl, d, pd, ol, q, T, w, bs, mx, cnt); break;
    case 3: process_unit<KLEN, 3>(xsl, d, pd, ol, q, T, w, bs, mx, cnt); break;
    case 4: process_unit<KLEN, 4>(xsl, d, pd, ol, q, T, w, bs, mx, cnt); break;
    default: process_unit<KLEN, 0>(xsl, d, pd, ol, q, T, w, bs, mx, cnt); break;
    }
}

__global__ void __launch_bounds__(32 * WARPS_PER_CTA, 3)
rf_main(const float* __restrict__ x,
        const float* __restrict__ w,
        const float* __restrict__ bias,
        const int*   __restrict__ dil,
        const int*   __restrict__ padr,
        const int*   __restrict__ olen,
        int B, int T, int K)
{
    extern __shared__ float xs[];                 // [T][32]
    const int lane = threadIdx.x & 31;
    const int warp = threadIdx.x >> 5;
    const int bg   = blockIdx.y;
    const int b0   = bg * 32;
    const int nb   = min(32, B - b0);

    // Transposed fill: coalesced LDG (consecutive t), conflict-free STS.
    for (int bb = warp; bb < 32; bb += WARPS_PER_CTA) {
        const int bsafe = min(bb, nb - 1);
        for (int t = lane; t < T; t += 32) {
            float v = x[(size_t)(b0 + bsafe) * T + t];
            xs[t * 32 + bb] = (bb < nb) ? v : 0.0f;
        }
    }
    __syncthreads();

    const float* xsl = xs + lane;
    const int nunits = K * NQ;

    for (;;) {
        int u = 0;
        if (lane == 0) u = atomicAdd(&g_ctr[bg], 1);
        u = __shfl_sync(0xFFFFFFFFu, u, 0);
        if (u >= nunits) break;

        const int k = u >> 2;
        const int q = u & (NQ - 1);
        const int   d  = dil[k];
        const int   pd = padr[k];
        const int   ol = olen[k];
        const float bv = bias[k];

        float wreg[MAX_KLEN];
#pragma unroll
        for (int j = 0; j < MAX_KLEN; j++)
            wreg[j] = __ldg(&w[(size_t)k * MAX_KLEN + j]);

        float mx  = -CUDART_INF_F;
        float cnt = 0.0f;

        if (d >= 1) {
            // klen inference: taps >= klen are exactly zero by construction.
            if (wreg[9] != 0.0f || wreg[10] != 0.0f)
                dispatch_d<11>(xsl, d, pd, ol, q, T, wreg, bv, mx, cnt);
            else if (wreg[7] != 0.0f || wreg[8] != 0.0f)
                dispatch_d<9>(xsl, d, pd, ol, q, T, wreg, bv, mx, cnt);
            else
                dispatch_d<7>(xsl, d, pd, ol, q, T, wreg, bv, mx, cnt);
        }

        float* s = g_scr + ((size_t)bg * KMAX * NQ + u) * 64;
        s[lane]      = mx;
        s[32 + lane] = cnt;
    }
}

__global__ void rf_fin(const int* __restrict__ olen,
                       float* __restrict__ out, int B, int K)
{
    const int bg = blockIdx.y;
    // Reset the work counter for the next graph replay (runs after rf_main).
    if (blockIdx.x == 0 && threadIdx.x == 0 && threadIdx.y == 0)
        g_ctr[bg] = 0;

    const int lane = threadIdx.x;                 // batch within group
    const int k    = blockIdx.x * blockDim.y + threadIdx.y;
    const int b    = bg * 32 + lane;
    if (k >= K) return;

    const float* s = g_scr + ((size_t)bg * KMAX * NQ + (size_t)k * NQ) * 64;
    float mx  = s[lane];
    float cnt = s[32 + lane];
#pragma unroll
    for (int q = 1; q < NQ; q++) {
        mx   = fmaxf(mx, s[q * 64 + lane]);
        cnt += s[q * 64 + 32 + lane];
    }
    if (b < B) {
        float* o = out + (size_t)b * 2 * K + 2 * k;
        o[0] = mx;
        o[1] = cnt / (float)olen[k];
    }
}

extern "C" void kernel_launch(void* const* d_in, const int* in_sizes, int n_in,
                              void* d_out, int out_size) {
    const float* x    = (const float*)d_in[0];
    const float* w    = (const float*)d_in[1];
    const float* bias = (const float*)d_in[2];
    const int*   dil  = (const int*)d_in[3];
    const int*   padr = (const int*)d_in[4];
    const int*   olen = (const int*)d_in[5];
    float* out = (float*)d_out;

    const int K = in_sizes[2];                 // bias element count
    const int B = out_size / (2 * K);
    const int T = in_sizes[0] / B;
    const int nbg = (B + 31) / 32;             // batch groups (<= BGMAX)

    const size_t smem = (size_t)T * 32 * sizeof(float);
    cudaFuncSetAttribute(rf_main,
                         cudaFuncAttributeMaxDynamicSharedMemorySize,
                         (int)smem);

    // ~3 CTAs/SM x 148 SMs persistent, split across batch groups.
    int ctas_per_bg = (444 + nbg - 1) / nbg;
    dim3 grid(ctas_per_bg, nbg);
    rf_main<<<grid, 32 * WARPS_PER_CTA, smem>>>(x, w, bias, dil, padr, olen,
                                                B, T, K);

    dim3 fblock(32, 8);
    dim3 fgrid((K + 7) / 8, nbg);
    rf_fin<<<fgrid, fblock>>>(olen, out, B, K);
}

// round 6
// speedup vs baseline: 5.2575x; 5.2575x over previous
#include <cuda_runtime.h>
#include <math_constants.h>

// RandomFeatures, round 6: round-4 structure + zero halo (no bounds checks),
// rf_init folded into rf_fin, 15 warps x 2 CTAs/SM.
// lane = batch; xs transposed [(HALO+T+HALO)][33] in shared; warp-uniform row
// index => bank = lane => conflict-free. Sliding-window register reuse per
// residue class; exact 8/4/2/1 block chain; dynamic quarter-units via atomic.

#define MAX_KLEN 11
#define WARPS_PER_CTA 15
#define XPITCH 33
#define HALO 128
#define NQ 4
#define BGMAX 4
#define KMAX 8192

__device__ int   g_ctr[BGMAX];          // zero-initialized; rf_fin re-zeroes
__device__ float g_scr[(size_t)BGMAX * KMAX * NQ * 64];

template<int KLEN, int NB>
__device__ __forceinline__ void conv_block(
    const float* __restrict__ p,     // &xs[(HALO+base)*XPITCH + lane]
    int dp,                          // d * XPITCH
    const float* __restrict__ w, float bs,
    float& mx, float& cnt)
{
    float Y[NB + KLEN - 1];
#pragma unroll
    for (int t = 0; t < NB + KLEN - 1; t++) Y[t] = p[t * dp];
#pragma unroll
    for (int i = 0; i < NB; i++) {
        float a = bs;
#pragma unroll
        for (int j = 0; j < KLEN; j++) a = fmaf(w[j], Y[i + j], a);
        mx = fmaxf(mx, a);
        cnt += (a > 0.0f) ? 1.0f : 0.0f;
    }
}

template<int KLEN>
__device__ __forceinline__ void conv_range(
    const float* __restrict__ xsl,   // xs + lane
    int r, int pd, int mlo, int mhi, int d, int dp,
    const float* __restrict__ w, float bs,
    float& mx, float& cnt)
{
    int m0 = mlo;
    const float* p = xsl + (HALO + r - pd + m0 * d) * XPITCH;
    for (; m0 + 8 <= mhi; m0 += 8) {
        conv_block<KLEN, 8>(p, dp, w, bs, mx, cnt);
        p += 8 * dp;
    }
    if (m0 + 4 <= mhi) { conv_block<KLEN, 4>(p, dp, w, bs, mx, cnt); m0 += 4; p += 4 * dp; }
    if (m0 + 2 <= mhi) { conv_block<KLEN, 2>(p, dp, w, bs, mx, cnt); m0 += 2; p += 2 * dp; }
    if (m0 < mhi)      { conv_block<KLEN, 1>(p, dp, w, bs, mx, cnt); }
}

template<int KLEN>
__device__ __forceinline__ void process_unit(
    const float* __restrict__ xsl, int d, int pd, int ol, int q,
    const float* __restrict__ w, float bs, float& mx, float& cnt)
{
    const int dp = d * XPITCH;
    const int q0 = (ol - 1) / d;                 // one division per unit
    const int rr = (ol - 1) - q0 * d;
    if (d >= NQ) {
        for (int r = q; r < d; r += NQ) {
            const int M = (r <= rr) ? q0 + 1 : q0;   // = ceil((ol-r)/d)
            conv_range<KLEN>(xsl, r, pd, 0, M, d, dp, w, bs, mx, cnt);
        }
    } else {
        for (int r = 0; r < d; r++) {
            const int M = (r <= rr) ? q0 + 1 : q0;
            conv_range<KLEN>(xsl, r, pd, (q * M) >> 2, ((q + 1) * M) >> 2,
                             d, dp, w, bs, mx, cnt);
        }
    }
}

// Safe fallback for parameters outside the halo guarantee (not expected).
template<int KLEN>
__device__ __forceinline__ void process_unit_safe(
    const float* __restrict__ xsl, int d, int pd, int ol, int q, int T,
    const float* __restrict__ w, float bs, float& mx, float& cnt)
{
    const int lo = (q * ol) >> 2, hi = ((q + 1) * ol) >> 2;
    for (int p = lo; p < hi; p++) {
        float a = bs;
#pragma unroll
        for (int j = 0; j < KLEN; j++) {
            const long long ix = (long long)p - pd + (long long)j * d;
            const int ixc = (int)min(max(ix, 0LL), (long long)(T - 1));
            float v = xsl[(HALO + ixc) * XPITCH];
            a = fmaf(w[j], (ix >= 0 && ix < T) ? v : 0.0f, a);
        }
        mx = fmaxf(mx, a);
        cnt += (a > 0.0f) ? 1.0f : 0.0f;
    }
}

__global__ void __launch_bounds__(32 * WARPS_PER_CTA, 2)
rf_main(const float* __restrict__ x,
        const float* __restrict__ w,
        const float* __restrict__ bias,
        const int*   __restrict__ dil,
        const int*   __restrict__ padr,
        const int*   __restrict__ olen,
        int B, int T, int K)
{
    extern __shared__ float xs[];                 // [(HALO+T+HALO)][XPITCH]
    const int lane = threadIdx.x & 31;
    const int warp = threadIdx.x >> 5;
    const int bg   = blockIdx.y;
    const int b0   = bg * 32;
    const int nb   = min(32, B - b0);

    // Transposed fill with zero halos: coalesced LDG, conflict-free STS (33 odd).
    for (int bb = warp; bb < 32; bb += WARPS_PER_CTA) {
        const int bsafe = min(bb, nb - 1);
        for (int t = lane; t < HALO; t += 32) {
            xs[t * XPITCH + bb] = 0.0f;
            xs[(HALO + T + t) * XPITCH + bb] = 0.0f;
        }
        for (int t = lane; t < T; t += 32) {
            float v = x[(size_t)(b0 + bsafe) * T + t];
            xs[(HALO + t) * XPITCH + bb] = (bb < nb) ? v : 0.0f;
        }
    }
    __syncthreads();

    const float* xsl = xs + lane;
    const int nunits = K * NQ;

    for (;;) {
        int u = 0;
        if (lane == 0) u = atomicAdd(&g_ctr[bg], 1);
        u = __shfl_sync(0xFFFFFFFFu, u, 0);
        if (u >= nunits) break;

        const int k = u >> 2;
        const int q = u & (NQ - 1);
        const int   d  = dil[k];
        const int   pd = padr[k];
        const int   ol = olen[k];
        const float bv = bias[k];

        float wreg[MAX_KLEN];
#pragma unroll
        for (int j = 0; j < MAX_KLEN; j++)
            wreg[j] = __ldg(&w[(size_t)k * MAX_KLEN + j]);

        float mx  = -CUDART_INF_F;
        float cnt = 0.0f;

        // klen inference: taps >= klen are exactly zero by construction.
        const int klen = (wreg[9] != 0.0f || wreg[10] != 0.0f) ? 11
                       : (wreg[7] != 0.0f || wreg[8] != 0.0f) ? 9 : 7;
        // Halo-safety: max |offset| is max(pd, ol-1-pd+(klen-1)d - (T-1)) <= pd
        // and right extent <= T-1+pd; guaranteed if pd < HALO and window fits.
        const bool safe = (d >= 1) && (pd < HALO) &&
                          ((ol - 1) - pd + (long long)(klen - 1) * d < T + HALO);

        if (safe) {
            if (klen == 11)      process_unit<11>(xsl, d, pd, ol, q, wreg, bv, mx, cnt);
            else if (klen == 9)  process_unit<9>(xsl, d, pd, ol, q, wreg, bv, mx, cnt);
            else                 process_unit<7>(xsl, d, pd, ol, q, wreg, bv, mx, cnt);
        } else if (d >= 1) {
            if (klen == 11)      process_unit_safe<11>(xsl, d, pd, ol, q, T, wreg, bv, mx, cnt);
            else if (klen == 9)  process_unit_safe<9>(xsl, d, pd, ol, q, T, wreg, bv, mx, cnt);
            else                 process_unit_safe<7>(xsl, d, pd, ol, q, T, wreg, bv, mx, cnt);
        }

        float* s = g_scr + ((size_t)bg * KMAX * NQ + u) * 64;
        s[lane]      = mx;
        s[32 + lane] = cnt;
    }
}

__global__ void rf_fin(const int* __restrict__ olen,
                       float* __restrict__ out, int B, int K)
{
    const int bg = blockIdx.y;
    // Reset the work counter for the next graph replay (runs after rf_main).
    if (blockIdx.x == 0 && threadIdx.x == 0 && threadIdx.y == 0)
        g_ctr[bg] = 0;

    const int lane = threadIdx.x;                 // batch within group
    const int k    = blockIdx.x * blockDim.y + threadIdx.y;
    const int b    = bg * 32 + lane;
    if (k >= K) return;

    const float* s = g_scr + ((size_t)bg * KMAX * NQ + (size_t)k * NQ) * 64;
    float mx  = s[lane];
    float cnt = s[32 + lane];
#pragma unroll
    for (int q = 1; q < NQ; q++) {
        mx   = fmaxf(mx, s[q * 64 + lane]);
        cnt += s[q * 64 + 32 + lane];
    }
    if (b < B) {
        float* o = out + (size_t)b * 2 * K + 2 * k;
        o[0] = mx;
        o[1] = cnt / (float)olen[k];
    }
}

extern "C" void kernel_launch(void* const* d_in, const int* in_sizes, int n_in,
                              void* d_out, int out_size) {
    const float* x    = (const float*)d_in[0];
    const float* w    = (const float*)d_in[1];
    const float* bias = (const float*)d_in[2];
    const int*   dil  = (const int*)d_in[3];
    const int*   padr = (const int*)d_in[4];
    const int*   olen = (const int*)d_in[5];
    float* out = (float*)d_out;

    const int K = in_sizes[2];                 // bias element count
    const int B = out_size / (2 * K);
    const int T = in_sizes[0] / B;
    const int nbg = (B + 31) / 32;             // batch groups (<= BGMAX)

    const size_t smem = (size_t)(2 * HALO + T) * XPITCH * sizeof(float);
    cudaFuncSetAttribute(rf_main,
                         cudaFuncAttributeMaxDynamicSharedMemorySize,
                         (int)smem);

    // 2 CTAs/SM x 148 SMs persistent, split across batch groups.
    int ctas_per_bg = (296 + nbg - 1) / nbg;
    dim3 grid(ctas_per_bg, nbg);
    rf_main<<<grid, 32 * WARPS_PER_CTA, smem>>>(x, w, bias, dil, padr, olen,
                                                B, T, K);

    dim3 fblock(32, 8);
    dim3 fgrid((K + 7) / 8, nbg);
    rf_fin<<<fgrid, fblock>>>(olen, out, B, K);
}